// round 8
// baseline (speedup 1.0000x reference)
#include <cuda_runtime.h>
#include <cuda_bf16.h>

#define BATCH 8192
#define TMAX  2048
#define ROWSTRIDE (TMAX + 1)   // 2049 ints per row (last element is T)
#define TILE 256               // 8 elements per lane

// 31-entry layered LUT: layer v (v=0..4) = products of v consecutive per-obs
// matrices, base = 2^v - 1, index = obs bits (chronologically first = LSB).
// float4 = (c00, c01, c10, c11); alpha' = C * alpha. Entry 0 = identity.

__global__ __launch_bounds__(256)
void hmm_fwd_kernel(const int* __restrict__ xin,
                    const float* __restrict__ prior_l,
                    const float* __restrict__ trans_l,
                    const float* __restrict__ emis_l,
                    float* __restrict__ out) {
    __shared__ float4 slut[31];

    const int tid  = threadIdx.x;
    const int wid  = tid >> 5;
    const int lane = tid & 31;
    const int row_id = blockIdx.x * 8 + wid;   // warp-per-row

    // ---- softmax constants (uniform, cheap, L1-cached) ----
    float pe0 = __expf(prior_l[0]), pe1 = __expf(prior_l[1]);
    float pinv = 1.0f / (pe0 + pe1);
    const float p0 = pe0 * pinv, p1 = pe1 * pinv;

    float t00 = __expf(trans_l[0]), t01 = __expf(trans_l[1]);
    float t10 = __expf(trans_l[2]), t11 = __expf(trans_l[3]);
    float rr0 = 1.0f / (t00 + t01), rr1 = 1.0f / (t10 + t11);
    const float A00 = t00 * rr0, A01 = t01 * rr0;
    const float A10 = t10 * rr1, A11 = t11 * rr1;

    float e00x = __expf(emis_l[0]), e01x = __expf(emis_l[1]);
    float e10x = __expf(emis_l[2]), e11x = __expf(emis_l[3]);
    float s0 = 1.0f / (e00x + e01x), s1 = 1.0f / (e10x + e11x);
    const float E00 = e00x * s0, E01 = e01x * s0;
    const float E10 = e10x * s1, E11 = e11x * s1;

    // per-obs step matrices: alpha' = M_x * alpha
    const float Ma00 = E00 * A00, Ma01 = E00 * A10, Ma10 = E10 * A01, Ma11 = E10 * A11;
    const float Mb00 = E01 * A00, Mb01 = E01 * A10, Mb10 = E11 * A01, Mb11 = E11 * A11;

    // ---- build 31-entry LUT: thread k builds entry k directly ----
    if (tid < 31) {
        const int n = tid + 1;
        const int v = 31 - __clz(n);           // layer
        const int idx = n - (1 << v);          // obs bits
        float c00 = 1.f, c01 = 0.f, c10 = 0.f, c11 = 1.f;
        for (int i = 0; i < v; ++i) {
            const int b = (idx >> i) & 1;
            const float m00 = b ? Mb00 : Ma00, m01 = b ? Mb01 : Ma01;
            const float m10 = b ? Mb10 : Ma10, m11 = b ? Mb11 : Ma11;
            const float q00 = m00 * c00 + m01 * c10;
            const float q01 = m00 * c01 + m01 * c11;
            const float q10 = m10 * c00 + m11 * c10;
            const float q11 = m10 * c01 + m11 * c11;
            c00 = q00; c01 = q01; c10 = q10; c11 = q11;
        }
        slut[tid] = make_float4(c00, c01, c10, c11);
    }
    __syncthreads();

    const int* __restrict__ row = xin + (size_t)row_id * ROWSTRIDE;
    const int T = row[TMAX];

    // alignment peel: want (row_id*2049 + t) ≡ 0 mod 4  (2049 ≡ 1 mod 4)
    const int mis = (row_id + 1) & 3;
    const int t0  = 1 + ((4 - mis) & 3);       // in [1,4]

    // running product r (identical on all lanes); peel elems [1, min(t0,T))
    float r00 = 1.f, r01 = 0.f, r10 = 0.f, r11 = 1.f;
    const int pe = t0 < T ? t0 : T;
    for (int t = 1; t < pe; ++t) {             // <=3 iters, broadcast loads
        const float4 M = slut[1 + row[t]];
        const float q00 = M.x * r00 + M.y * r10;
        const float q01 = M.x * r01 + M.y * r11;
        const float q10 = M.z * r00 + M.w * r10;
        const float q11 = M.z * r01 + M.w * r11;
        r00 = q00; r01 = q01; r10 = q10; r11 = q11;
    }

    // tiles of 256 steps; in practice exactly one executes (underflow break)
    for (int s = t0; s < T; s += TILE) {
        const int pos = s + (lane << 3);       // this lane's 8 contiguous elems

        int4 a = make_int4(0, 0, 0, 0), b = a;
        if (pos < T) {
            if (pos + 8 <= ROWSTRIDE) {        // inside row storage (aligned)
                const int4* p = (const int4*)(row + pos);
                a = p[0]; b = p[1];
            } else {                            // rare tail at the very row end
                const int v = T - pos;          // <= 6 here
                a.x = row[pos];
                if (v > 1) a.y = row[pos + 1];
                if (v > 2) a.z = row[pos + 2];
                if (v > 3) a.w = row[pos + 3];
                if (v > 4) b.x = row[pos + 4];
                if (v > 5) b.y = row[pos + 5];
            }
        }

        // pack bits; out-of-range words masked by the layer select below
        const int idxA = a.x + 2 * a.y + 4 * a.z + 8 * a.w;
        const int idxB = b.x + 2 * b.y + 4 * b.z + 8 * b.w;

        int rem = T - pos;
        rem = rem < 0 ? 0 : (rem > 8 ? 8 : rem);
        const int vA = rem < 4 ? rem : 4;
        const int vB = rem - vA;

        const float4 MA = slut[((1 << vA) - 1) + (idxA & ((1 << vA) - 1))];
        const float4 MB = slut[((1 << vB) - 1) + (idxB & ((1 << vB) - 1))];

        // lane's 8-step product: C = MB * MA
        float c00 = MB.x * MA.x + MB.y * MA.z;
        float c01 = MB.x * MA.y + MB.y * MA.w;
        float c10 = MB.z * MA.x + MB.w * MA.z;
        float c11 = MB.z * MA.y + MB.w * MA.w;

        // ordered XOR-butterfly all-reduce: every lane ends with the full
        // chronological product  P = C_31 * C_30 * ... * C_0
        #pragma unroll
        for (int d = 1; d < 32; d <<= 1) {
            const float u00 = __shfl_xor_sync(0xFFFFFFFFu, c00, d);
            const float u01 = __shfl_xor_sync(0xFFFFFFFFu, c01, d);
            const float u10 = __shfl_xor_sync(0xFFFFFFFFu, c10, d);
            const float u11 = __shfl_xor_sync(0xFFFFFFFFu, c11, d);
            const bool later = (lane & d) != 0;     // my range is later in time
            // c_new = (later-range matrix) * (earlier-range matrix)
            const float L00 = later ? c00 : u00, L01 = later ? c01 : u01;
            const float L10 = later ? c10 : u10, L11 = later ? c11 : u11;
            const float R00 = later ? u00 : c00, R01 = later ? u01 : c01;
            const float R10 = later ? u10 : c10, R11 = later ? u11 : c11;
            c00 = L00 * R00 + L01 * R10;
            c01 = L00 * R01 + L01 * R11;
            c10 = L10 * R00 + L11 * R10;
            c11 = L10 * R01 + L11 * R11;
        }

        // fold tile product (identical on all lanes)
        {
            const float q00 = c00 * r00 + c01 * r10;
            const float q01 = c00 * r01 + c01 * r11;
            const float q10 = c10 * r00 + c11 * r10;
            const float q11 = c10 * r01 + c11 * r11;
            r00 = q00; r01 = q01; r10 = q10; r11 = q11;
        }

        // all entries are nonnegative products: sum == 0 <=> product is zero.
        // Once zero it stays zero -> remaining timesteps cannot change out.
        if (r00 + r01 + r10 + r11 == 0.0f) break;   // warp-uniform
    }

    if (lane == 0) {
        const int x0 = row[0];
        const float al0 = (x0 ? E01 : E00) * p0;
        const float al1 = (x0 ? E11 : E10) * p1;
        out[row_id] = (r00 * al0 + r01 * al1) + (r10 * al0 + r11 * al1);
    }
}

extern "C" void kernel_launch(void* const* d_in, const int* in_sizes, int n_in,
                              void* d_out, int out_size) {
    const int*   xin     = (const int*)d_in[0];
    const float* prior_l = (const float*)d_in[1];
    const float* trans_l = (const float*)d_in[2];
    const float* emis_l  = (const float*)d_in[3];
    float* out = (float*)d_out;

    const int blocks = BATCH / 8;      // 1024 blocks, 8 warps, warp-per-row
    hmm_fwd_kernel<<<blocks, 256>>>(xin, prior_l, trans_l, emis_l, out);
}

// round 9
// speedup vs baseline: 2.4607x; 2.4607x over previous
#include <cuda_runtime.h>
#include <cuda_bf16.h>

#define BATCH 8192
#define TMAX  2048
#define ROWSTRIDE (TMAX + 1)   // 2049 ints per row (last element is T)
#define TILE 256               // 8 elements per lane, warp-per-row

// 31-entry layered LUT: layer v (v=0..4) = products of v consecutive per-obs
// matrices, base = 2^v - 1, index = obs bits (chronologically first = LSB).
// float4 = (c00, c01, c10, c11); alpha' = C * alpha. Entry 0 = identity.

// Reduce lane-chunk matrices (chronological, lane 0 earliest) into lane 0,
// fold into running product r (lane 0 only), return broadcast of fold-sum.
__device__ __forceinline__ float reduce_fold(float c00, float c01, float c10, float c11,
                                             float& r00, float& r01, float& r10, float& r11,
                                             int lane) {
    #pragma unroll
    for (int d = 1; d < 32; d <<= 1) {
        const float u00 = __shfl_down_sync(0xFFFFFFFFu, c00, d);
        const float u01 = __shfl_down_sync(0xFFFFFFFFu, c01, d);
        const float u10 = __shfl_down_sync(0xFFFFFFFFu, c10, d);
        const float u11 = __shfl_down_sync(0xFFFFFFFFu, c11, d);
        if (lane + d < 32) {                    // u is LATER in time: c = u * c
            const float q00 = u00 * c00 + u01 * c10;
            const float q01 = u00 * c01 + u01 * c11;
            const float q10 = u10 * c00 + u11 * c10;
            const float q11 = u10 * c01 + u11 * c11;
            c00 = q00; c01 = q01; c10 = q10; c11 = q11;
        }
    }
    if (lane == 0) {
        const float q00 = c00 * r00 + c01 * r10;
        const float q01 = c00 * r01 + c01 * r11;
        const float q10 = c10 * r00 + c11 * r10;
        const float q11 = c10 * r01 + c11 * r11;
        r00 = q00; r01 = q01; r10 = q10; r11 = q11;
    }
    // nonneg entries: sum == 0 <=> product exactly zero (then it stays zero)
    const float s = r00 + r01 + r10 + r11;
    return __shfl_sync(0xFFFFFFFFu, s, 0);
}

__global__ __launch_bounds__(256)
void hmm_fwd_kernel(const int* __restrict__ xin,
                    const float* __restrict__ prior_l,
                    const float* __restrict__ trans_l,
                    const float* __restrict__ emis_l,
                    float* __restrict__ out) {
    __shared__ float4 slut[31];
    __shared__ float2 a0tab[2];    // a0tab[x0] = alpha0 vector

    const int tid  = threadIdx.x;
    const int wid  = tid >> 5;
    const int lane = tid & 31;
    const int row_id = blockIdx.x * 8 + wid;

    const int* __restrict__ row = xin + (size_t)row_id * ROWSTRIDE;

    // ---- issue all independent loads up front (overlap with LUT build) ----
    const int T  = row[TMAX];
    const int x0 = row[0];
    const int mis = (row_id + 1) & 3;          // row base ≡ row_id+? mod 4 ints
    const int t0  = 1 + ((4 - mis) & 3);       // 16B-aligned start, in [1,4]
    const int pk1 = (t0 > 1) ? row[1] : 0;     // peel observations
    const int pk2 = (t0 > 2) ? row[2] : 0;
    const int pk3 = (t0 > 3) ? row[3] : 0;

    // first tile: pos <= 252, always in-bounds -> unconditional vector loads
    const int pos0 = t0 + (lane << 3);
    const int4* p0 = (const int4*)(row + pos0);
    const int4 fa = p0[0];
    const int4 fb = p0[1];

    // ---- warp 0: constants + LUT + alpha0 table (others go wait at sync) ----
    if (wid == 0) {
        float pe0 = __expf(prior_l[0]), pe1 = __expf(prior_l[1]);
        float pinv = 1.0f / (pe0 + pe1);
        const float p0f = pe0 * pinv, p1f = pe1 * pinv;

        float t00 = __expf(trans_l[0]), t01 = __expf(trans_l[1]);
        float t10 = __expf(trans_l[2]), t11 = __expf(trans_l[3]);
        float rr0 = 1.0f / (t00 + t01), rr1 = 1.0f / (t10 + t11);
        const float A00 = t00 * rr0, A01 = t01 * rr0;
        const float A10 = t10 * rr1, A11 = t11 * rr1;

        float e00x = __expf(emis_l[0]), e01x = __expf(emis_l[1]);
        float e10x = __expf(emis_l[2]), e11x = __expf(emis_l[3]);
        float s0 = 1.0f / (e00x + e01x), s1 = 1.0f / (e10x + e11x);
        const float E00 = e00x * s0, E01 = e01x * s0;
        const float E10 = e10x * s1, E11 = e11x * s1;

        const float Ma00 = E00 * A00, Ma01 = E00 * A10, Ma10 = E10 * A01, Ma11 = E10 * A11;
        const float Mb00 = E01 * A00, Mb01 = E01 * A10, Mb10 = E11 * A01, Mb11 = E11 * A11;

        if (lane == 31) {
            a0tab[0] = make_float2(E00 * p0f, E10 * p1f);
            a0tab[1] = make_float2(E01 * p0f, E11 * p1f);
        } else {
            const int n = lane + 1;              // entry n-1? no: entry index lane
            const int v = 31 - __clz(n);         // layer of entry (n = lane+1)
            const int idx = n - (1 << v);
            float c00 = 1.f, c01 = 0.f, c10 = 0.f, c11 = 1.f;
            for (int i = 0; i < v; ++i) {
                const int b = (idx >> i) & 1;
                const float m00 = b ? Mb00 : Ma00, m01 = b ? Mb01 : Ma01;
                const float m10 = b ? Mb10 : Ma10, m11 = b ? Mb11 : Ma11;
                const float q00 = m00 * c00 + m01 * c10;
                const float q01 = m00 * c01 + m01 * c11;
                const float q10 = m10 * c00 + m11 * c10;
                const float q11 = m10 * c01 + m11 * c11;
                c00 = q00; c01 = q01; c10 = q10; c11 = q11;
            }
            slut[lane] = make_float4(c00, c01, c10, c11);
        }
    }
    __syncthreads();

    // ---- peel elements [1, min(t0,T)) via LUT layer 1 ----
    float r00 = 1.f, r01 = 0.f, r10 = 0.f, r11 = 1.f;
    const int pe = t0 < T ? t0 : T;
    if (pe > 1) { const float4 M = slut[1 + pk1]; r00 = M.x; r01 = M.y; r10 = M.z; r11 = M.w; }
    if (pe > 2) {
        const float4 M = slut[1 + pk2];
        const float q00 = M.x * r00 + M.y * r10, q01 = M.x * r01 + M.y * r11;
        const float q10 = M.z * r00 + M.w * r10, q11 = M.z * r01 + M.w * r11;
        r00 = q00; r01 = q01; r10 = q10; r11 = q11;
    }
    if (pe > 3) {
        const float4 M = slut[1 + pk3];
        const float q00 = M.x * r00 + M.y * r10, q01 = M.x * r01 + M.y * r11;
        const float q10 = M.z * r00 + M.w * r10, q11 = M.z * r01 + M.w * r11;
        r00 = q00; r01 = q01; r10 = q10; r11 = q11;
    }

    if (t0 < T) {
        // ---- first tile (data already in registers) ----
        {
            const int idxA = fa.x + 2 * fa.y + 4 * fa.z + 8 * fa.w;
            const int idxB = fb.x + 2 * fb.y + 4 * fb.z + 8 * fb.w;
            int rem = T - pos0;
            rem = rem < 0 ? 0 : (rem > 8 ? 8 : rem);
            const int vA = rem < 4 ? rem : 4;
            const int vB = rem - vA;
            const float4 MA = slut[((1 << vA) - 1) + (idxA & ((1 << vA) - 1))];
            const float4 MB = slut[((1 << vB) - 1) + (idxB & ((1 << vB) - 1))];
            const float c00 = MB.x * MA.x + MB.y * MA.z;
            const float c01 = MB.x * MA.y + MB.y * MA.w;
            const float c10 = MB.z * MA.x + MB.w * MA.z;
            const float c11 = MB.z * MA.y + MB.w * MA.w;
            float sum = reduce_fold(c00, c01, c10, c11, r00, r01, r10, r11, lane);

            // ---- later tiles: rare (run only if no underflow yet) ----
            for (int s = t0 + TILE; s < T && sum != 0.0f; s += TILE) {
                const int pos = s + (lane << 3);
                int4 a = make_int4(0, 0, 0, 0), b = a;
                if (pos < T) {
                    if (pos + 8 <= ROWSTRIDE) {
                        const int4* p = (const int4*)(row + pos);
                        a = p[0]; b = p[1];
                    } else {                       // tail at the very row end
                        const int v = T - pos;     // <= 6 here
                        a.x = row[pos];
                        if (v > 1) a.y = row[pos + 1];
                        if (v > 2) a.z = row[pos + 2];
                        if (v > 3) a.w = row[pos + 3];
                        if (v > 4) b.x = row[pos + 4];
                        if (v > 5) b.y = row[pos + 5];
                    }
                }
                const int idxA2 = a.x + 2 * a.y + 4 * a.z + 8 * a.w;
                const int idxB2 = b.x + 2 * b.y + 4 * b.z + 8 * b.w;
                int rem2 = T - pos;
                rem2 = rem2 < 0 ? 0 : (rem2 > 8 ? 8 : rem2);
                const int vA2 = rem2 < 4 ? rem2 : 4;
                const int vB2 = rem2 - vA2;
                const float4 MA2 = slut[((1 << vA2) - 1) + (idxA2 & ((1 << vA2) - 1))];
                const float4 MB2 = slut[((1 << vB2) - 1) + (idxB2 & ((1 << vB2) - 1))];
                const float d00 = MB2.x * MA2.x + MB2.y * MA2.z;
                const float d01 = MB2.x * MA2.y + MB2.y * MA2.w;
                const float d10 = MB2.z * MA2.x + MB2.w * MA2.z;
                const float d11 = MB2.z * MA2.y + MB2.w * MA2.w;
                sum = reduce_fold(d00, d01, d10, d11, r00, r01, r10, r11, lane);
            }
        }
    }

    if (lane == 0) {
        const float2 al = a0tab[x0];
        out[row_id] = (r00 * al.x + r01 * al.y) + (r10 * al.x + r11 * al.y);
    }
}

extern "C" void kernel_launch(void* const* d_in, const int* in_sizes, int n_in,
                              void* d_out, int out_size) {
    const int*   xin     = (const int*)d_in[0];
    const float* prior_l = (const float*)d_in[1];
    const float* trans_l = (const float*)d_in[2];
    const float* emis_l  = (const float*)d_in[3];
    float* out = (float*)d_out;

    const int blocks = BATCH / 8;      // 1024 blocks, 8 warps, warp-per-row
    hmm_fwd_kernel<<<blocks, 256>>>(xin, prior_l, trans_l, emis_l, out);
}